// round 7
// baseline (speedup 1.0000x reference)
#include <cuda_runtime.h>
#include <cuda_bf16.h>
#include <mma.h>

using namespace nvcuda;

#define XN 16777216   // 16*32*32*1024
#define WN 1048576    // 1024*1024

__device__ __nv_bfloat16 g_x1h[XN];
__device__ __nv_bfloat16 g_x1l[XN];
__device__ __nv_bfloat16 g_x2h[XN];
__device__ __nv_bfloat16 g_x2l[XN];
__device__ __nv_bfloat16 g_wth[3 * WN];
__device__ __nv_bfloat16 g_wtl[3 * WN];
__device__ float g_Yq[XN];
__device__ float g_Yk[XN];
__device__ float g_Yv[XN];
__device__ float g_O[XN];

// ---- 1) split activations fp32 -> (hi,lo) bf16 ----
__global__ void split_x_kernel(const float* __restrict__ x, int which) {
    int i = blockIdx.x * blockDim.x + threadIdx.x;   // float4 index
    float4 v = reinterpret_cast<const float4*>(x)[i];
    __nv_bfloat16* __restrict__ h = which ? g_x2h : g_x1h;
    __nv_bfloat16* __restrict__ l = which ? g_x2l : g_x1l;
    __nv_bfloat16 h0 = __float2bfloat16(v.x), h1 = __float2bfloat16(v.y);
    __nv_bfloat16 h2 = __float2bfloat16(v.z), h3 = __float2bfloat16(v.w);
    __nv_bfloat16 l0 = __float2bfloat16(v.x - __bfloat162float(h0));
    __nv_bfloat16 l1 = __float2bfloat16(v.y - __bfloat162float(h1));
    __nv_bfloat16 l2 = __float2bfloat16(v.z - __bfloat162float(h2));
    __nv_bfloat16 l3 = __float2bfloat16(v.w - __bfloat162float(h3));
    __nv_bfloat162* hp = reinterpret_cast<__nv_bfloat162*>(h) + 2 * i;
    __nv_bfloat162* lp = reinterpret_cast<__nv_bfloat162*>(l) + 2 * i;
    hp[0] = __halves2bfloat162(h0, h1); hp[1] = __halves2bfloat162(h2, h3);
    lp[0] = __halves2bfloat162(l0, l1); lp[1] = __halves2bfloat162(l2, l3);
}

// ---- 2) weights: Wt[k][n] = W[n][k], split hi/lo ----
__global__ void wsplit_kernel(const float* __restrict__ W, int wi) {
    __shared__ float s[32][33];
    int t = threadIdx.x, bx = blockIdx.x, by = blockIdx.y;
#pragma unroll
    for (int i = 0; i < 4; i++) {
        int idx = t + i * 256, nn = idx >> 5, kk = idx & 31;
        s[nn][kk] = W[(by * 32 + nn) * 1024 + bx * 32 + kk];
    }
    __syncthreads();
    __nv_bfloat16* __restrict__ th = g_wth + wi * WN;
    __nv_bfloat16* __restrict__ tl = g_wtl + wi * WN;
#pragma unroll
    for (int i = 0; i < 4; i++) {
        int idx = t + i * 256, kk = idx >> 5, nn = idx & 31;
        float v = s[nn][kk];
        __nv_bfloat16 h = __float2bfloat16(v);
        int o = (bx * 32 + kk) * 1024 + by * 32 + nn;
        th[o] = h;
        tl[o] = __float2bfloat16(v - __bfloat162float(h));
    }
}

// ---- 3) GEMM Y = X @ Wt, bf16x3, 128x128 tile, BK=32, 8 warps ----
__global__ void __launch_bounds__(256) gemm_kernel() {
    int z = blockIdx.z;
    const __nv_bfloat16* Ah = (z == 0) ? g_x1h : g_x2h;
    const __nv_bfloat16* Al = (z == 0) ? g_x1l : g_x2l;
    const __nv_bfloat16* Bh = g_wth + z * WN;
    const __nv_bfloat16* Bl = g_wtl + z * WN;
    float* Y = (z == 0) ? g_Yq : ((z == 1) ? g_Yk : g_Yv);

    __shared__ __nv_bfloat16 sA[2][128][48];
    __shared__ __nv_bfloat16 sB[2][32][144];

    int t = threadIdx.x, warp = t >> 5;
    int wm = warp & 3, wn = warp >> 2;
    int rb = blockIdx.y * 128, cb = blockIdx.x * 128;

    wmma::fragment<wmma::accumulator, 16, 16, 16, float> acc[2][4];
#pragma unroll
    for (int mi = 0; mi < 2; mi++)
#pragma unroll
        for (int ni = 0; ni < 4; ni++) wmma::fill_fragment(acc[mi][ni], 0.0f);

    for (int kt = 0; kt < 32; kt++) {
#pragma unroll
        for (int i = 0; i < 2; i++) {
            int idx = t + i * 256, row = idx >> 2, q = idx & 3;
            const uint4* sh = reinterpret_cast<const uint4*>(Ah + (rb + row) * 1024 + kt * 32) + q;
            const uint4* sl = reinterpret_cast<const uint4*>(Al + (rb + row) * 1024 + kt * 32) + q;
            *reinterpret_cast<uint4*>(&sA[0][row][q * 8]) = *sh;
            *reinterpret_cast<uint4*>(&sA[1][row][q * 8]) = *sl;
        }
#pragma unroll
        for (int i = 0; i < 2; i++) {
            int idx = t + i * 256, kk = idx >> 4, q = idx & 15;
            const uint4* sh = reinterpret_cast<const uint4*>(Bh + (kt * 32 + kk) * 1024 + cb) + q;
            const uint4* sl = reinterpret_cast<const uint4*>(Bl + (kt * 32 + kk) * 1024 + cb) + q;
            *reinterpret_cast<uint4*>(&sB[0][kk][q * 8]) = *sh;
            *reinterpret_cast<uint4*>(&sB[1][kk][q * 8]) = *sl;
        }
        __syncthreads();
#pragma unroll
        for (int kk2 = 0; kk2 < 2; kk2++) {
            wmma::fragment<wmma::matrix_a, 16, 16, 16, __nv_bfloat16, wmma::row_major> ah[2], al[2];
            wmma::fragment<wmma::matrix_b, 16, 16, 16, __nv_bfloat16, wmma::row_major> bh[4], bl[4];
#pragma unroll
            for (int mi = 0; mi < 2; mi++) {
                wmma::load_matrix_sync(ah[mi], &sA[0][wm * 32 + mi * 16][kk2 * 16], 48);
                wmma::load_matrix_sync(al[mi], &sA[1][wm * 32 + mi * 16][kk2 * 16], 48);
            }
#pragma unroll
            for (int ni = 0; ni < 4; ni++) {
                wmma::load_matrix_sync(bh[ni], &sB[0][kk2 * 16][wn * 64 + ni * 16], 144);
                wmma::load_matrix_sync(bl[ni], &sB[1][kk2 * 16][wn * 64 + ni * 16], 144);
            }
#pragma unroll
            for (int mi = 0; mi < 2; mi++)
#pragma unroll
                for (int ni = 0; ni < 4; ni++) {
                    wmma::mma_sync(acc[mi][ni], ah[mi], bh[ni], acc[mi][ni]);
                    wmma::mma_sync(acc[mi][ni], ah[mi], bl[ni], acc[mi][ni]);
                    wmma::mma_sync(acc[mi][ni], al[mi], bh[ni], acc[mi][ni]);
                }
        }
        __syncthreads();
    }
#pragma unroll
    for (int mi = 0; mi < 2; mi++)
#pragma unroll
        for (int ni = 0; ni < 4; ni++)
            wmma::store_matrix_sync(Y + (rb + wm * 32 + mi * 16) * 1024 + cb + wn * 64 + ni * 16,
                                    acc[mi][ni], 1024, wmma::mem_row_major);
}

// ---- 4) attention: warp per unit (b,i,j); lane = l2 column ----
// E[r,l] = sum_h (Yq[b,h,i,r*32+j]+bq[r*32+j]) * (Yk[b,i,j,h*32+l]+bk[h*32+l])
// A = softmax_l(E); O[r,l] = sum_t (Yv[b,i,j,r*32+t]+bv[r*32+t]) * A[t,l]
__global__ void __launch_bounds__(128) attn_kernel(const float* __restrict__ bq,
                                                   const float* __restrict__ bk,
                                                   const float* __restrict__ bv) {
    __shared__ float qs[4][32][33];
    __shared__ float vs[4][32][33];
    int w = threadIdx.x >> 5, lane = threadIdx.x & 31;
    int u = blockIdx.x * 4 + w;
    int b = u >> 10, i = (u >> 5) & 31, j = u & 31;

    const float* Krow = g_Yk + ((b * 32 + i) * 32 + j) * 1024;
    const float* Vrow = g_Yv + ((b * 32 + i) * 32 + j) * 1024;

    float kreg[32];
#pragma unroll
    for (int h = 0; h < 32; h++)
        kreg[h] = Krow[h * 32 + lane] + bk[h * 32 + lane];
#pragma unroll
    for (int r = 0; r < 32; r++)
        vs[w][r][lane] = Vrow[r * 32 + lane] + bv[r * 32 + lane];
#pragma unroll
    for (int r = 0; r < 32; r++)
        qs[w][r][lane] = g_Yq[((b * 32 + lane) * 32 + i) * 1024 + r * 32 + j] + bq[r * 32 + j];
    __syncwarp();

    float a[32];
#pragma unroll
    for (int r = 0; r < 32; r++) {
        float e = 0.f;
#pragma unroll
        for (int h = 0; h < 32; h++) e = fmaf(qs[w][r][h], kreg[h], e);
        float m = e;
#pragma unroll
        for (int o = 16; o > 0; o >>= 1) m = fmaxf(m, __shfl_xor_sync(0xffffffffu, m, o));
        float p = __expf(e - m);
        float s = p;
#pragma unroll
        for (int o = 16; o > 0; o >>= 1) s += __shfl_xor_sync(0xffffffffu, s, o);
        a[r] = p * __frcp_rn(s);
    }

    float* Orow = g_O + ((b * 32 + i) * 32 + j) * 1024;
#pragma unroll
    for (int r = 0; r < 32; r++) {
        float o = 0.f;
#pragma unroll
        for (int t = 0; t < 32; t++) o = fmaf(vs[w][r][t], a[t], o);
        Orow[r * 32 + lane] = o;
    }
}

// ---- 5) output transpose: out[b,j,l, r*32+i] = g_O[b,i,j, r*32+l] ----
__global__ void otrans_kernel(float* __restrict__ out) {
    __shared__ float s[32][33];
    int t = threadIdx.x;
    int b = blockIdx.x >> 5, j = blockIdx.x & 31;
    for (int r = 0; r < 32; r++) {
        __syncthreads();
#pragma unroll
        for (int k = 0; k < 4; k++) {
            int idx = t + k * 256, i = idx >> 5, l = idx & 31;
            s[i][l] = g_O[((b * 32 + i) * 32 + j) * 1024 + r * 32 + l];
        }
        __syncthreads();
#pragma unroll
        for (int k = 0; k < 4; k++) {
            int idx = t + k * 256, l = idx >> 5, i = idx & 31;
            out[((b * 32 + j) * 32 + l) * 1024 + r * 32 + i] = s[i][l];
        }
    }
}

extern "C" void kernel_launch(void* const* d_in, const int* in_sizes, int n_in,
                              void* d_out, int out_size) {
    const float* x1 = (const float*)d_in[0];
    const float* x2 = (const float*)d_in[1];
    const float* Wq = (const float*)d_in[2];
    const float* bq = (const float*)d_in[3];
    const float* Wk = (const float*)d_in[4];
    const float* bk = (const float*)d_in[5];
    const float* Wv = (const float*)d_in[6];
    const float* bv = (const float*)d_in[7];
    float* out = (float*)d_out;

    split_x_kernel<<<16384, 256>>>(x1, 0);
    split_x_kernel<<<16384, 256>>>(x2, 1);
    wsplit_kernel<<<dim3(32, 32), 256>>>(Wq, 0);
    wsplit_kernel<<<dim3(32, 32), 256>>>(Wk, 1);
    wsplit_kernel<<<dim3(32, 32), 256>>>(Wv, 2);
    gemm_kernel<<<dim3(8, 128, 3), 256>>>();
    attn_kernel<<<4096, 128>>>(bq, bk, bv);
    otrans_kernel<<<512, 256>>>(out);
}

// round 9
// speedup vs baseline: 1.1555x; 1.1555x over previous
#include <cuda_runtime.h>
#include <cuda_bf16.h>
#include <mma.h>
#include <cstdint>

using namespace nvcuda;

#define XN 16777216   // 16*32*32*1024
#define WN 1048576    // 1024*1024

__device__ __nv_bfloat16 g_x1h[XN];
__device__ __nv_bfloat16 g_x1l[XN];
__device__ __nv_bfloat16 g_x2h[XN];
__device__ __nv_bfloat16 g_x2l[XN];
__device__ __nv_bfloat16 g_wth[3 * WN];
__device__ __nv_bfloat16 g_wtl[3 * WN];
__device__ float g_Yq[XN];
__device__ float g_Yk[XN];
__device__ float g_Yv[XN];
__device__ float g_O[XN];

// ---- 1) split activations fp32 -> (hi,lo) bf16 ----
__global__ void split_x_kernel(const float* __restrict__ x, int which) {
    int i = blockIdx.x * blockDim.x + threadIdx.x;   // float4 index
    float4 v = reinterpret_cast<const float4*>(x)[i];
    __nv_bfloat16* __restrict__ h = which ? g_x2h : g_x1h;
    __nv_bfloat16* __restrict__ l = which ? g_x2l : g_x1l;
    __nv_bfloat16 h0 = __float2bfloat16(v.x), h1 = __float2bfloat16(v.y);
    __nv_bfloat16 h2 = __float2bfloat16(v.z), h3 = __float2bfloat16(v.w);
    __nv_bfloat16 l0 = __float2bfloat16(v.x - __bfloat162float(h0));
    __nv_bfloat16 l1 = __float2bfloat16(v.y - __bfloat162float(h1));
    __nv_bfloat16 l2 = __float2bfloat16(v.z - __bfloat162float(h2));
    __nv_bfloat16 l3 = __float2bfloat16(v.w - __bfloat162float(h3));
    __nv_bfloat162* hp = reinterpret_cast<__nv_bfloat162*>(h) + 2 * i;
    __nv_bfloat162* lp = reinterpret_cast<__nv_bfloat162*>(l) + 2 * i;
    hp[0] = __halves2bfloat162(h0, h1); hp[1] = __halves2bfloat162(h2, h3);
    lp[0] = __halves2bfloat162(l0, l1); lp[1] = __halves2bfloat162(l2, l3);
}

// ---- 2) weights: Wt[k][n] = W[n][k], split hi/lo ----
__global__ void wsplit_kernel(const float* __restrict__ W, int wi) {
    __shared__ float s[32][33];
    int t = threadIdx.x, bx = blockIdx.x, by = blockIdx.y;
#pragma unroll
    for (int i = 0; i < 4; i++) {
        int idx = t + i * 256, nn = idx >> 5, kk = idx & 31;
        s[nn][kk] = W[(by * 32 + nn) * 1024 + bx * 32 + kk];
    }
    __syncthreads();
    __nv_bfloat16* __restrict__ th = g_wth + wi * WN;
    __nv_bfloat16* __restrict__ tl = g_wtl + wi * WN;
#pragma unroll
    for (int i = 0; i < 4; i++) {
        int idx = t + i * 256, kk = idx >> 5, nn = idx & 31;
        float v = s[nn][kk];
        __nv_bfloat16 h = __float2bfloat16(v);
        int o = (bx * 32 + kk) * 1024 + by * 32 + nn;
        th[o] = h;
        tl[o] = __float2bfloat16(v - __bfloat162float(h));
    }
}

// ---- cp.async helpers ----
__device__ __forceinline__ void cpasync16(unsigned int s, const void* g) {
    asm volatile("cp.async.cg.shared.global [%0], [%1], 16;" :: "r"(s), "l"(g));
}
__device__ __forceinline__ void cpasync_commit() {
    asm volatile("cp.async.commit_group;");
}
template <int N>
__device__ __forceinline__ void cpasync_wait() {
    asm volatile("cp.async.wait_group %0;" :: "n"(N));
}

// ---- 3) GEMM Y = X @ Wt, bf16x3, 128x128 tile, BK=32, double-buffered cp.async ----
// dynamic smem layout (elements of bf16):
//   sA: [(stage*2+hl)][128][48]   base 0,      unit 6144
//   sB: [(stage*2+hl)][32][144]   base 24576,  unit 4608
// total = 43008 elems = 86016 bytes
#define SA_UNIT 6144
#define SB_BASE 24576
#define SB_UNIT 4608

extern __shared__ __nv_bfloat16 g_smem[];

__global__ void __launch_bounds__(256) gemm_kernel() {
    int z = blockIdx.z;
    const __nv_bfloat16* Ah = (z == 0) ? g_x1h : g_x2h;
    const __nv_bfloat16* Al = (z == 0) ? g_x1l : g_x2l;
    const __nv_bfloat16* Bh = g_wth + z * WN;
    const __nv_bfloat16* Bl = g_wtl + z * WN;
    float* Y = (z == 0) ? g_Yq : ((z == 1) ? g_Yk : g_Yv);

    int t = threadIdx.x, warp = t >> 5;
    int wm = warp & 3, wn = warp >> 2;
    int rb = blockIdx.y * 128, cb = blockIdx.x * 128;

    unsigned int sbase = (unsigned int)__cvta_generic_to_shared(g_smem);

    wmma::fragment<wmma::accumulator, 16, 16, 16, float> acc[2][4];
#pragma unroll
    for (int mi = 0; mi < 2; mi++)
#pragma unroll
        for (int ni = 0; ni < 4; ni++) wmma::fill_fragment(acc[mi][ni], 0.0f);

    // precomputed per-thread staging coordinates
    int arow0 = t >> 2, aq0 = t & 3;
    int arow1 = (t + 256) >> 2, aq1 = (t + 256) & 3;
    int bkk0 = t >> 4, bq0 = t & 15;
    int bkk1 = (t + 256) >> 4, bq1 = (t + 256) & 15;

#define STAGE_LOAD(stage, kt)                                                              \
    do {                                                                                   \
        int _kc = (kt) * 32;                                                               \
        cpasync16(sbase + (((stage) * 2 + 0) * SA_UNIT + arow0 * 48 + aq0 * 8) * 2,        \
                  Ah + (rb + arow0) * 1024 + _kc + aq0 * 8);                               \
        cpasync16(sbase + (((stage) * 2 + 1) * SA_UNIT + arow0 * 48 + aq0 * 8) * 2,        \
                  Al + (rb + arow0) * 1024 + _kc + aq0 * 8);                               \
        cpasync16(sbase + (((stage) * 2 + 0) * SA_UNIT + arow1 * 48 + aq1 * 8) * 2,        \
                  Ah + (rb + arow1) * 1024 + _kc + aq1 * 8);                               \
        cpasync16(sbase + (((stage) * 2 + 1) * SA_UNIT + arow1 * 48 + aq1 * 8) * 2,        \
                  Al + (rb + arow1) * 1024 + _kc + aq1 * 8);                               \
        cpasync16(sbase + (SB_BASE + ((stage) * 2 + 0) * SB_UNIT + bkk0 * 144 + bq0 * 8) * 2, \
                  Bh + (_kc + bkk0) * 1024 + cb + bq0 * 8);                                \
        cpasync16(sbase + (SB_BASE + ((stage) * 2 + 1) * SB_UNIT + bkk0 * 144 + bq0 * 8) * 2, \
                  Bl + (_kc + bkk0) * 1024 + cb + bq0 * 8);                                \
        cpasync16(sbase + (SB_BASE + ((stage) * 2 + 0) * SB_UNIT + bkk1 * 144 + bq1 * 8) * 2, \
                  Bh + (_kc + bkk1) * 1024 + cb + bq1 * 8);                                \
        cpasync16(sbase + (SB_BASE + ((stage) * 2 + 1) * SB_UNIT + bkk1 * 144 + bq1 * 8) * 2, \
                  Bl + (_kc + bkk1) * 1024 + cb + bq1 * 8);                                \
        cpasync_commit();                                                                  \
    } while (0)

    STAGE_LOAD(0, 0);

    for (int kt = 0; kt < 32; kt++) {
        int stage = kt & 1;
        if (kt + 1 < 32) {
            STAGE_LOAD(stage ^ 1, kt + 1);
            cpasync_wait<1>();
        } else {
            cpasync_wait<0>();
        }
        __syncthreads();

        const __nv_bfloat16* A0 = g_smem + (stage * 2 + 0) * SA_UNIT;
        const __nv_bfloat16* A1 = g_smem + (stage * 2 + 1) * SA_UNIT;
        const __nv_bfloat16* B0 = g_smem + SB_BASE + (stage * 2 + 0) * SB_UNIT;
        const __nv_bfloat16* B1 = g_smem + SB_BASE + (stage * 2 + 1) * SB_UNIT;

#pragma unroll
        for (int kk2 = 0; kk2 < 2; kk2++) {
            wmma::fragment<wmma::matrix_a, 16, 16, 16, __nv_bfloat16, wmma::row_major> ah[2], al[2];
            wmma::fragment<wmma::matrix_b, 16, 16, 16, __nv_bfloat16, wmma::row_major> bh[4], bl[4];
#pragma unroll
            for (int mi = 0; mi < 2; mi++) {
                wmma::load_matrix_sync(ah[mi], A0 + (wm * 32 + mi * 16) * 48 + kk2 * 16, 48);
                wmma::load_matrix_sync(al[mi], A1 + (wm * 32 + mi * 16) * 48 + kk2 * 16, 48);
            }
#pragma unroll
            for (int ni = 0; ni < 4; ni++) {
                wmma::load_matrix_sync(bh[ni], B0 + (kk2 * 16) * 144 + wn * 64 + ni * 16, 144);
                wmma::load_matrix_sync(bl[ni], B1 + (kk2 * 16) * 144 + wn * 64 + ni * 16, 144);
            }
#pragma unroll
            for (int mi = 0; mi < 2; mi++)
#pragma unroll
                for (int ni = 0; ni < 4; ni++) {
                    wmma::mma_sync(acc[mi][ni], ah[mi], bh[ni], acc[mi][ni]);
                    wmma::mma_sync(acc[mi][ni], ah[mi], bl[ni], acc[mi][ni]);
                    wmma::mma_sync(acc[mi][ni], al[mi], bh[ni], acc[mi][ni]);
                }
        }
        __syncthreads();
    }

#pragma unroll
    for (int mi = 0; mi < 2; mi++)
#pragma unroll
        for (int ni = 0; ni < 4; ni++)
            wmma::store_matrix_sync(Y + (rb + wm * 32 + mi * 16) * 1024 + cb + wn * 64 + ni * 16,
                                    acc[mi][ni], 1024, wmma::mem_row_major);
}

// ---- 4) attention: warp per unit (b,i,j); lane = l2 column ----
__global__ void __launch_bounds__(128) attn_kernel(const float* __restrict__ bq,
                                                   const float* __restrict__ bk,
                                                   const float* __restrict__ bv) {
    __shared__ float qs[4][32][33];
    __shared__ float vs[4][32][33];
    int w = threadIdx.x >> 5, lane = threadIdx.x & 31;
    int u = blockIdx.x * 4 + w;
    int b = u >> 10, i = (u >> 5) & 31, j = u & 31;

    const float* Krow = g_Yk + ((b * 32 + i) * 32 + j) * 1024;
    const float* Vrow = g_Yv + ((b * 32 + i) * 32 + j) * 1024;

    float kreg[32];
#pragma unroll
    for (int h = 0; h < 32; h++)
        kreg[h] = Krow[h * 32 + lane] + bk[h * 32 + lane];
#pragma unroll
    for (int r = 0; r < 32; r++)
        vs[w][r][lane] = Vrow[r * 32 + lane] + bv[r * 32 + lane];
#pragma unroll
    for (int r = 0; r < 32; r++)
        qs[w][r][lane] = g_Yq[((b * 32 + lane) * 32 + i) * 1024 + r * 32 + j] + bq[r * 32 + j];
    __syncwarp();

    float a[32];
#pragma unroll
    for (int r = 0; r < 32; r++) {
        float e = 0.f;
#pragma unroll
        for (int h = 0; h < 32; h++) e = fmaf(qs[w][r][h], kreg[h], e);
        float m = e;
#pragma unroll
        for (int o = 16; o > 0; o >>= 1) m = fmaxf(m, __shfl_xor_sync(0xffffffffu, m, o));
        float p = __expf(e - m);
        float s = p;
#pragma unroll
        for (int o = 16; o > 0; o >>= 1) s += __shfl_xor_sync(0xffffffffu, s, o);
        a[r] = p * __frcp_rn(s);
    }

    float* Orow = g_O + ((b * 32 + i) * 32 + j) * 1024;
#pragma unroll
    for (int r = 0; r < 32; r++) {
        float o = 0.f;
#pragma unroll
        for (int t = 0; t < 32; t++) o = fmaf(vs[w][r][t], a[t], o);
        Orow[r * 32 + lane] = o;
    }
}

// ---- 5) output transpose: out[b,j,l, r*32+i] = g_O[b,i,j, r*32+l] ----
__global__ void otrans_kernel(float* __restrict__ out) {
    __shared__ float s[32][33];
    int t = threadIdx.x;
    int b = blockIdx.x >> 5, j = blockIdx.x & 31;
    for (int r = 0; r < 32; r++) {
        __syncthreads();
#pragma unroll
        for (int k = 0; k < 4; k++) {
            int idx = t + k * 256, i = idx >> 5, l = idx & 31;
            s[i][l] = g_O[((b * 32 + i) * 32 + j) * 1024 + r * 32 + l];
        }
        __syncthreads();
#pragma unroll
        for (int k = 0; k < 4; k++) {
            int idx = t + k * 256, l = idx >> 5, i = idx & 31;
            out[((b * 32 + j) * 32 + l) * 1024 + r * 32 + i] = s[i][l];
        }
    }
}

extern "C" void kernel_launch(void* const* d_in, const int* in_sizes, int n_in,
                              void* d_out, int out_size) {
    const float* x1 = (const float*)d_in[0];
    const float* x2 = (const float*)d_in[1];
    const float* Wq = (const float*)d_in[2];
    const float* bq = (const float*)d_in[3];
    const float* Wk = (const float*)d_in[4];
    const float* bk = (const float*)d_in[5];
    const float* Wv = (const float*)d_in[6];
    const float* bv = (const float*)d_in[7];
    float* out = (float*)d_out;

    cudaFuncSetAttribute(gemm_kernel, cudaFuncAttributeMaxDynamicSharedMemorySize, 86016);

    split_x_kernel<<<16384, 256>>>(x1, 0);
    split_x_kernel<<<16384, 256>>>(x2, 1);
    wsplit_kernel<<<dim3(32, 32), 256>>>(Wq, 0);
    wsplit_kernel<<<dim3(32, 32), 256>>>(Wk, 1);
    wsplit_kernel<<<dim3(32, 32), 256>>>(Wv, 2);
    gemm_kernel<<<dim3(8, 128, 3), 256, 86016>>>();
    attn_kernel<<<4096, 128>>>(bq, bk, bv);
    otrans_kernel<<<512, 256>>>(out);
}